// round 1
// baseline (speedup 1.0000x reference)
#include <cuda_runtime.h>

// SlidingWindowMatrixMult3D: Z[b,w,t] = sum_c Q[b,w,c]*K[b,w+t,c] + sum_c Q[b,w,c]*bias[c,t]
// B=16, T=1024, C=128.  K has 2T-1 = 2047 rows.  Output (B,T,T) fp32.
//
// Fused single kernel: each CTA computes a 128(w) x 128(t) tile of Z.
// Needed K rows for the tile: [w0+t0, w0+t0+254] (255 rows) — always in range.
// Inner fused form: acc[i][j] += q[i] * (K[i+j] + bias[j]).

#define Bz 16
#define Tz 1024
#define Cz 128
#define KTOT (2 * Tz - 1)

#define TM 128
#define TN 128
#define KC 16            // c-chunk per smem stage
#define KROWS (TM + TN - 1)   // 255 K rows per tile
#define KPAD 256

__global__ __launch_bounds__(256, 2)
void swmm3d_kernel(const float* __restrict__ Q,
                   const float* __restrict__ K,
                   const float* __restrict__ bias,
                   float* __restrict__ Z)
{
    __shared__ float Qs[KC][TM];    // 8 KB  (c-major, transposed)
    __shared__ float Ks[KC][KPAD];  // 16 KB (c-major, transposed; 255 used)
    __shared__ float Bs[KC][TN];    // 8 KB  (bias already c-major)

    const int b  = blockIdx.z;
    const int w0 = blockIdx.y * TM;
    const int t0 = blockIdx.x * TN;
    const int kbase = w0 + t0;      // first K row needed by this tile

    const float* __restrict__ Qb = Q + (size_t)b * Tz * Cz;
    const float* __restrict__ Kb = K + (size_t)b * KTOT * Cz;

    const int tid = threadIdx.x;
    const int tx = tid & 15;        // 16 x 16 thread grid
    const int ty = tid >> 4;
    const int i0 = ty * 8;          // row offset within tile (w)
    const int j0 = tx * 8;          // col offset within tile (t)
    const int k0 = i0 + j0;         // K-row offset within Ks for this micro-tile

    float acc[8][8];
    #pragma unroll
    for (int i = 0; i < 8; i++)
        #pragma unroll
        for (int j = 0; j < 8; j++)
            acc[i][j] = 0.0f;

    for (int c0 = 0; c0 < Cz; c0 += KC) {
        // ---- Load Q chunk, transposed into Qs[cc][row]  (128 rows x 16 c) ----
        #pragma unroll
        for (int f = tid; f < (TM * KC) / 4; f += 256) {  // 512 float4s
            int row = f >> 2;
            int cg  = f & 3;
            float4 v = *(const float4*)(Qb + (size_t)(w0 + row) * Cz + c0 + cg * 4);
            Qs[cg * 4 + 0][row] = v.x;
            Qs[cg * 4 + 1][row] = v.y;
            Qs[cg * 4 + 2][row] = v.z;
            Qs[cg * 4 + 3][row] = v.w;
        }
        // ---- Load K chunk, transposed into Ks[cc][row]  (255 rows x 16 c) ----
        for (int f = tid; f < (KROWS * KC) / 4; f += 256) {  // 1020 float4s
            int row = f >> 2;
            int cg  = f & 3;
            float4 v = *(const float4*)(Kb + (size_t)(kbase + row) * Cz + c0 + cg * 4);
            Ks[cg * 4 + 0][row] = v.x;
            Ks[cg * 4 + 1][row] = v.y;
            Ks[cg * 4 + 2][row] = v.z;
            Ks[cg * 4 + 3][row] = v.w;
        }
        // ---- Load bias chunk: Bs[cc][j] — bias layout is already (C, T) ----
        #pragma unroll
        for (int f = tid; f < (KC * TN) / 4; f += 256) {  // 512 float4s
            int cc = f >> 5;       // TN/4 = 32 float4s per c-row
            int jg = f & 31;
            float4 v = *(const float4*)(bias + (size_t)(c0 + cc) * Tz + t0 + jg * 4);
            *(float4*)&Bs[cc][jg * 4] = v;
        }
        __syncthreads();

        // ---- Compute: acc[i][j] += q[i] * (k[i+j] + bias[j]) ----
        #pragma unroll
        for (int cc = 0; cc < KC; cc++) {
            float qf[8], kf[16], bf[8];
            *(float4*)&qf[0] = *(const float4*)&Qs[cc][i0];
            *(float4*)&qf[4] = *(const float4*)&Qs[cc][i0 + 4];
            *(float4*)&kf[0]  = *(const float4*)&Ks[cc][k0];
            *(float4*)&kf[4]  = *(const float4*)&Ks[cc][k0 + 4];
            *(float4*)&kf[8]  = *(const float4*)&Ks[cc][k0 + 8];
            *(float4*)&kf[12] = *(const float4*)&Ks[cc][k0 + 12];
            *(float4*)&bf[0] = *(const float4*)&Bs[cc][j0];
            *(float4*)&bf[4] = *(const float4*)&Bs[cc][j0 + 4];

            #pragma unroll
            for (int i = 0; i < 8; i++) {
                #pragma unroll
                for (int j = 0; j < 8; j++) {
                    acc[i][j] += qf[i] * (kf[i + j] + bf[j]);
                }
            }
        }
        __syncthreads();
    }

    // ---- Store Z tile ----
    float* __restrict__ Zb = Z + ((size_t)b * Tz + w0) * Tz + t0;
    #pragma unroll
    for (int i = 0; i < 8; i++) {
        float4* dst = (float4*)(Zb + (size_t)(i0 + i) * Tz + j0);
        dst[0] = make_float4(acc[i][0], acc[i][1], acc[i][2], acc[i][3]);
        dst[1] = make_float4(acc[i][4], acc[i][5], acc[i][6], acc[i][7]);
    }
}

extern "C" void kernel_launch(void* const* d_in, const int* in_sizes, int n_in,
                              void* d_out, int out_size)
{
    const float* Q    = (const float*)d_in[0];   // (16, 1024, 128)
    const float* K    = (const float*)d_in[1];   // (16, 2047, 128)
    const float* bias = (const float*)d_in[2];   // (1, 1, 128, 1024)
    float* Z = (float*)d_out;                    // (16, 1024, 1024)

    dim3 grid(Tz / TN, Tz / TM, Bz);  // (8, 8, 16) = 1024 CTAs
    dim3 block(256);
    swmm3d_kernel<<<grid, block>>>(Q, K, bias, Z);
}

// round 3
// speedup vs baseline: 1.0628x; 1.0628x over previous
#include <cuda_runtime.h>
#include <cuda_bf16.h>
#include <stdint.h>

// SlidingWindowMatrixMult3D via mma.sync bf16 (HMMA path; tcgen05 unavailable:
// harness PTX target is sm_103 without the 'a' feature set).
//
// Z[b,w,t] = sum_c Q[b,w,c]*K[b,w+t,c] + sum_c Q[b,w,c]*bias[c,t]
// B=16, T=1024, C=128.
//
// Per CTA: 128(w) x 128(t) output tile.
//  - bias term: P = Q_tile @ bias_cols^T  -> register accumulators (per warp 32x64)
//  - band term: S[i][n] = Q_tile[i,:] . K[kbase+n,:], n in [i, i+127] only.
//    Computed bandwise per warp (12 n-tiles of 8), scattered sheared into
//    smem Zs[i][n-i]. Final: Z = Zs + P.
//  - fp32 emulated as bf16 hi/lo, 3 MMA passes (hh, lh, hl).

#define Bz 16
#define Tz 1024
#define Cz 128
#define KTOT (2 * Tz - 1)

#define BFS 136              // bf16 row stride (136*2 = 272 B; conflict-free LDS.32)
#define ZSS 132              // Zs fp32 row stride

#define OFF_QH 0u
#define OFF_QL (OFF_QH + 128u * BFS * 2u)
#define OFF_BH (OFF_QL + 128u * BFS * 2u)
#define OFF_BL (OFF_BH + 128u * BFS * 2u)
#define OFF_ZS (OFF_BL + 128u * BFS * 2u)
#define SMEM_BYTES (OFF_ZS + 128u * ZSS * 4u)   // 206848 B

// ---------------------------------------------------------------------------
__device__ __forceinline__ void mma_bf16(float* d, const uint32_t* a,
                                         uint32_t b0, uint32_t b1) {
    asm volatile(
        "mma.sync.aligned.m16n8k16.row.col.f32.bf16.bf16.f32 "
        "{%0,%1,%2,%3}, {%4,%5,%6,%7}, {%8,%9}, {%0,%1,%2,%3};"
        : "+f"(d[0]), "+f"(d[1]), "+f"(d[2]), "+f"(d[3])
        : "r"(a[0]), "r"(a[1]), "r"(a[2]), "r"(a[3]), "r"(b0), "r"(b1));
}

__device__ __forceinline__ uint32_t ld32(const __nv_bfloat16* p) {
    return *(const uint32_t*)p;
}

// split a float4 into hi/lo bf16 pairs, return packed {h01,h23} and {l01,l23}
__device__ __forceinline__ void split4(float4 v, uint2& h, uint2& l) {
    __nv_bfloat162 h01 = __floats2bfloat162_rn(v.x, v.y);
    __nv_bfloat162 h23 = __floats2bfloat162_rn(v.z, v.w);
    float2 f01 = __bfloat1622float2(h01);
    float2 f23 = __bfloat1622float2(h23);
    __nv_bfloat162 l01 = __floats2bfloat162_rn(v.x - f01.x, v.y - f01.y);
    __nv_bfloat162 l23 = __floats2bfloat162_rn(v.z - f23.x, v.w - f23.y);
    h.x = *(uint32_t*)&h01; h.y = *(uint32_t*)&h23;
    l.x = *(uint32_t*)&l01; l.y = *(uint32_t*)&l23;
}

// convert nrows x 128 fp32 rows (contiguous) -> hi/lo bf16, row stride BFS
__device__ __forceinline__ void conv_rows(const float* __restrict__ src, int nrows,
                                          __nv_bfloat16* hi, __nv_bfloat16* lo, int tid) {
    const float4* s4 = (const float4*)src;
    for (int idx = tid; idx < nrows * 32; idx += 256) {
        int row = idx >> 5, cg = idx & 31;
        float4 v = __ldg(s4 + row * 32 + cg);
        uint2 h, l;
        split4(v, h, l);
        *(uint2*)(hi + row * BFS + cg * 4) = h;
        *(uint2*)(lo + row * BFS + cg * 4) = l;
    }
}

// bias (C x T) -> rows = t (n-major), cols = c, hi/lo bf16
__device__ __forceinline__ void conv_bias(const float* __restrict__ bias, int t0,
                                          __nv_bfloat16* hi, __nv_bfloat16* lo, int tid) {
    for (int idx = tid; idx < 4096; idx += 256) {
        int t = idx & 127;
        int cq = idx >> 7;             // group of 4 c values
        const float* bp = bias + (size_t)(cq * 4) * Tz + t0 + t;
        float4 v;
        v.x = __ldg(bp);
        v.y = __ldg(bp + Tz);
        v.z = __ldg(bp + 2 * Tz);
        v.w = __ldg(bp + 3 * Tz);
        uint2 h, l;
        split4(v, h, l);
        *(uint2*)(hi + t * BFS + cq * 4) = h;
        *(uint2*)(lo + t * BFS + cq * 4) = l;
    }
}

// ---------------------------------------------------------------------------
__global__ void __launch_bounds__(256, 1)
swmm3d_mma_kernel(const float* __restrict__ Q,
                  const float* __restrict__ K,
                  const float* __restrict__ bias,
                  float* __restrict__ Z)
{
    extern __shared__ char sm[];
    __nv_bfloat16* Qh = (__nv_bfloat16*)(sm + OFF_QH);
    __nv_bfloat16* Ql = (__nv_bfloat16*)(sm + OFF_QL);
    __nv_bfloat16* Bh = (__nv_bfloat16*)(sm + OFF_BH);
    __nv_bfloat16* Bl = (__nv_bfloat16*)(sm + OFF_BL);
    float* Zs = (float*)(sm + OFF_ZS);

    const int tid  = threadIdx.x;
    const int wid  = tid >> 5;
    const int lane = tid & 31;
    const int lr = lane >> 2;          // 0..7
    const int lc = (lane & 3) * 2;     // 0,2,4,6

    const int iw0 = (wid & 3) * 32;    // warp's output rows [iw0, iw0+32)
    const int jw0 = (wid >> 2) * 64;   // warp's output cols [jw0, jw0+64)

    const int b  = blockIdx.z;
    const int w0 = blockIdx.y * 128;
    const int t0 = blockIdx.x * 128;
    const int kbase = w0 + t0;

    // ---- conversions: Q tile and bias tile ----
    conv_rows(Q + ((size_t)b * Tz + w0) * Cz, 128, Qh, Ql, tid);
    conv_bias(bias, t0, Bh, Bl, tid);
    __syncthreads();

    // ---- bias GEMM: acc[mt][nt][4], warp region 32 x 64 ----
    float acc[2][8][4];
    #pragma unroll
    for (int mt = 0; mt < 2; mt++)
        #pragma unroll
        for (int nt = 0; nt < 8; nt++)
            #pragma unroll
            for (int e = 0; e < 4; e++)
                acc[mt][nt][e] = 0.0f;

    #pragma unroll 1
    for (int kt = 0; kt < 8; kt++) {
        const int ac = kt * 16 + lc;
        uint32_t Ah[2][4], Al[2][4];
        #pragma unroll
        for (int mt = 0; mt < 2; mt++) {
            const int ar = iw0 + mt * 16 + lr;
            const __nv_bfloat16* qh = Qh + ar * BFS + ac;
            const __nv_bfloat16* ql = Ql + ar * BFS + ac;
            Ah[mt][0] = ld32(qh);
            Ah[mt][1] = ld32(qh + 8 * BFS);
            Ah[mt][2] = ld32(qh + 8);
            Ah[mt][3] = ld32(qh + 8 * BFS + 8);
            Al[mt][0] = ld32(ql);
            Al[mt][1] = ld32(ql + 8 * BFS);
            Al[mt][2] = ld32(ql + 8);
            Al[mt][3] = ld32(ql + 8 * BFS + 8);
        }
        #pragma unroll
        for (int nt = 0; nt < 8; nt++) {
            const int bn = jw0 + nt * 8 + lr;
            uint32_t B0h = ld32(Bh + bn * BFS + ac);
            uint32_t B1h = ld32(Bh + bn * BFS + ac + 8);
            uint32_t B0l = ld32(Bl + bn * BFS + ac);
            uint32_t B1l = ld32(Bl + bn * BFS + ac + 8);
            #pragma unroll
            for (int mt = 0; mt < 2; mt++) {
                mma_bf16(acc[mt][nt], Ah[mt], B0h, B1h);
                mma_bf16(acc[mt][nt], Al[mt], B0h, B1h);
                mma_bf16(acc[mt][nt], Ah[mt], B0l, B1l);
            }
        }
    }

    // ---- band term, two K-row chunks of 128 / 127 rows ----
    const int ntg0 = (iw0 + jw0) >> 3;   // first global n-tile (aligned)
    #pragma unroll 1
    for (int ch = 0; ch < 2; ch++) {
        __syncthreads();                  // previous users of Bh/Bl done
        conv_rows(K + ((size_t)b * KTOT + kbase + ch * 128) * Cz,
                  ch ? 127 : 128, Bh, Bl, tid);
        __syncthreads();

        #pragma unroll 1
        for (int ntg = ntg0; ntg < ntg0 + 12; ntg++) {
            if ((ntg >> 4) != ch) continue;       // tile not in this chunk
            float s[2][4];
            #pragma unroll
            for (int mt = 0; mt < 2; mt++)
                #pragma unroll
                for (int e = 0; e < 4; e++) s[mt][e] = 0.0f;

            const int bn = (ntg & 15) * 8 + lr;   // local B row
            #pragma unroll
            for (int kt = 0; kt < 8; kt++) {
                const int ac = kt * 16 + lc;
                uint32_t B0h = ld32(Bh + bn * BFS + ac);
                uint32_t B1h = ld32(Bh + bn * BFS + ac + 8);
                uint32_t B0l = ld32(Bl + bn * BFS + ac);
                uint32_t B1l = ld32(Bl + bn * BFS + ac + 8);
                #pragma unroll
                for (int mt = 0; mt < 2; mt++) {
                    const int ar = iw0 + mt * 16 + lr;
                    const __nv_bfloat16* qh = Qh + ar * BFS + ac;
                    const __nv_bfloat16* ql = Ql + ar * BFS + ac;
                    uint32_t A_[4], Al_[4];
                    A_[0] = ld32(qh);
                    A_[1] = ld32(qh + 8 * BFS);
                    A_[2] = ld32(qh + 8);
                    A_[3] = ld32(qh + 8 * BFS + 8);
                    Al_[0] = ld32(ql);
                    Al_[1] = ld32(ql + 8 * BFS);
                    Al_[2] = ld32(ql + 8);
                    Al_[3] = ld32(ql + 8 * BFS + 8);
                    mma_bf16(s[mt], A_, B0h, B1h);
                    mma_bf16(s[mt], Al_, B0h, B1h);
                    mma_bf16(s[mt], A_, B0l, B1l);
                }
            }
            // scatter sheared: Zs[i][n - i], only this warp's j range
            #pragma unroll
            for (int mt = 0; mt < 2; mt++) {
                const int r0 = iw0 + mt * 16 + lr;
                const int nc = ntg * 8 + lc;
                int j;
                j = nc - r0;
                if ((unsigned)(j - jw0) < 64u) Zs[r0 * ZSS + j] = s[mt][0];
                j = nc + 1 - r0;
                if ((unsigned)(j - jw0) < 64u) Zs[r0 * ZSS + j] = s[mt][1];
                j = nc - (r0 + 8);
                if ((unsigned)(j - jw0) < 64u) Zs[(r0 + 8) * ZSS + j] = s[mt][2];
                j = nc + 1 - (r0 + 8);
                if ((unsigned)(j - jw0) < 64u) Zs[(r0 + 8) * ZSS + j] = s[mt][3];
            }
        }
    }

    __syncwarp();   // each warp reads only its own Zs region

    // ---- final: Z = Zs (band) + acc (bias) ----
    float* __restrict__ Zb = Z + ((size_t)b * Tz + w0) * Tz + t0;
    #pragma unroll
    for (int nt = 0; nt < 8; nt++) {
        const int c = jw0 + nt * 8 + lc;
        #pragma unroll
        for (int mt = 0; mt < 2; mt++) {
            const int r = iw0 + mt * 16 + lr;
            float2 o0;
            o0.x = acc[mt][nt][0] + Zs[r * ZSS + c];
            o0.y = acc[mt][nt][1] + Zs[r * ZSS + c + 1];
            *(float2*)(Zb + (size_t)r * Tz + c) = o0;
            float2 o1;
            o1.x = acc[mt][nt][2] + Zs[(r + 8) * ZSS + c];
            o1.y = acc[mt][nt][3] + Zs[(r + 8) * ZSS + c + 1];
            *(float2*)(Zb + (size_t)(r + 8) * Tz + c) = o1;
        }
    }
}

// ---------------------------------------------------------------------------
extern "C" void kernel_launch(void* const* d_in, const int* in_sizes, int n_in,
                              void* d_out, int out_size)
{
    const float* Q    = (const float*)d_in[0];   // (16, 1024, 128)
    const float* K    = (const float*)d_in[1];   // (16, 2047, 128)
    const float* bias = (const float*)d_in[2];   // (128, 1024)
    float* Z = (float*)d_out;                    // (16, 1024, 1024)

    static int configured = 0;
    if (!configured) {
        cudaFuncSetAttribute(swmm3d_mma_kernel,
                             cudaFuncAttributeMaxDynamicSharedMemorySize, SMEM_BYTES);
        configured = 1;
    }

    dim3 grid(Tz / 128, Tz / 128, Bz);  // (8, 8, 16) = 1024 CTAs
    swmm3d_mma_kernel<<<grid, 256, SMEM_BYTES>>>(Q, K, bias, Z);
}

// round 4
// speedup vs baseline: 1.2608x; 1.1863x over previous
#include <cuda_runtime.h>
#include <cuda_bf16.h>
#include <stdint.h>

// SlidingWindowMatrixMult3D via mma.sync bf16 (HMMA; tcgen05 not available on
// this harness's sm_103 base target).
// Z[b,w,t] = sum_c Q[b,w,c]*K[b,w+t,c] + sum_c Q[b,w,c]*bias[c,t]
// B=16, T=1024, C=128.
//
// Pre-pass kernels convert fp32 -> bf16 hi/lo into __device__ global arrays
// (Q, K as-is; bias transposed to t-major). Main kernel per CTA computes a
// 128x128 tile: band S scattered sheared directly to Z, then bias GEMM RMW
// Z += Q@bias^T. 3-pass bf16 split (hh, lh, hl) ~ fp32 accuracy.

#define Bz 16
#define Tz 1024
#define Cz 128
#define KTOT 2047

// ---- global bf16 scratch (static __device__, no allocations) ----
__device__ __nv_bfloat16 g_Qh[Bz * Tz * Cz];
__device__ __nv_bfloat16 g_Ql[Bz * Tz * Cz];
__device__ __nv_bfloat16 g_Kh[Bz * KTOT * Cz];
__device__ __nv_bfloat16 g_Kl[Bz * KTOT * Cz];
__device__ __nv_bfloat16 g_Bh[Tz * Cz];     // transposed: [t][c]
__device__ __nv_bfloat16 g_Bl[Tz * Cz];

// ---- smem layout (bytes); rows padded to 272 B (136 bf16) ----
#define RSTRIDE 272u
#define OFF_QH 0u
#define OFF_QL 34816u
#define OFF_KH 69632u            // 256-row buffer (K band / bias tile)
#define OFF_KL 139264u
#define SMEM_BYTES 208896u

// ---------------------------------------------------------------------------
__device__ __forceinline__ uint32_t cvta_sh(const void* p) {
    uint32_t a;
    asm("{ .reg .u64 t; cvta.to.shared.u64 t, %1; cvt.u32.u64 %0, t; }"
        : "=r"(a) : "l"(p));
    return a;
}

__device__ __forceinline__ void cp16(uint32_t d, const void* s) {
    asm volatile("cp.async.ca.shared.global [%0], [%1], 16;" :: "r"(d), "l"(s));
}
#define CP_WAIT_ALL() asm volatile("cp.async.wait_all;" ::: "memory")

__device__ __forceinline__ void ldsm4(uint32_t* r, uint32_t a) {
    asm volatile("ldmatrix.sync.aligned.m8n8.x4.shared.b16 {%0,%1,%2,%3}, [%4];"
                 : "=r"(r[0]), "=r"(r[1]), "=r"(r[2]), "=r"(r[3]) : "r"(a));
}

__device__ __forceinline__ void mma_bf16(float* d, const uint32_t* a,
                                         uint32_t b0, uint32_t b1) {
    asm volatile(
        "mma.sync.aligned.m16n8k16.row.col.f32.bf16.bf16.f32 "
        "{%0,%1,%2,%3}, {%4,%5,%6,%7}, {%8,%9}, {%0,%1,%2,%3};"
        : "+f"(d[0]), "+f"(d[1]), "+f"(d[2]), "+f"(d[3])
        : "r"(a[0]), "r"(a[1]), "r"(a[2]), "r"(a[3]), "r"(b0), "r"(b1));
}

// ---------------------------------------------------------------------------
// Pre-pass 1: Q and K fp32 -> bf16 hi/lo (elementwise, vectorized)
__global__ void conv_qk_kernel(const float* __restrict__ Q,
                               const float* __restrict__ K)
{
    const int nQ = Bz * Tz * Cz / 4;        // 524288 float4s
    const int nK = Bz * KTOT * Cz / 4;      // 1048064 float4s
    int i = blockIdx.x * blockDim.x + threadIdx.x;
    if (i >= nQ + nK) return;
    const float4* src;
    uint2 *dh, *dl;
    int j;
    if (i < nQ) { src = (const float4*)Q; dh = (uint2*)g_Qh; dl = (uint2*)g_Ql; j = i; }
    else        { src = (const float4*)K; dh = (uint2*)g_Kh; dl = (uint2*)g_Kl; j = i - nQ; }
    float4 v = __ldg(src + j);
    __nv_bfloat162 h01 = __floats2bfloat162_rn(v.x, v.y);
    __nv_bfloat162 h23 = __floats2bfloat162_rn(v.z, v.w);
    float2 f01 = __bfloat1622float2(h01);
    float2 f23 = __bfloat1622float2(h23);
    __nv_bfloat162 l01 = __floats2bfloat162_rn(v.x - f01.x, v.y - f01.y);
    __nv_bfloat162 l23 = __floats2bfloat162_rn(v.z - f23.x, v.w - f23.y);
    uint2 h, l;
    h.x = *(uint32_t*)&h01; h.y = *(uint32_t*)&h23;
    l.x = *(uint32_t*)&l01; l.y = *(uint32_t*)&l23;
    dh[j] = h;
    dl[j] = l;
}

// Pre-pass 2: bias (C x T) -> transposed (T x C) bf16 hi/lo
__global__ void conv_bias_kernel(const float* __restrict__ bias)
{
    int o = blockIdx.x * blockDim.x + threadIdx.x;
    if (o >= Tz * Cz) return;
    int t = o >> 7, c = o & 127;
    float v = __ldg(bias + c * Tz + t);
    __nv_bfloat16 h = __float2bfloat16(v);
    g_Bh[o] = h;
    g_Bl[o] = __float2bfloat16(v - __bfloat162float(h));
}

// ---------------------------------------------------------------------------
__global__ void __launch_bounds__(256, 1)
swmm3d_main(float* __restrict__ Z)
{
    extern __shared__ char sm[];
    const uint32_t sb = cvta_sh(sm);

    const int tid  = threadIdx.x;
    const int wid  = tid >> 5;        // 0..7  (owns output rows [16w, 16w+16))
    const int lane = tid & 31;
    const int lr = lane >> 2;         // 0..7
    const int lc = (lane & 3) * 2;    // 0,2,4,6

    const int b  = blockIdx.z;
    const int w0 = blockIdx.y * 128;
    const int t0 = blockIdx.x * 128;
    const int kbase = w0 + t0;

    // ---- phase 1: async-load Q tile (128 rows) and K band (255 rows) ----
    {
        const char* qh = (const char*)g_Qh + (size_t)(b * Tz + w0) * 256;
        const char* ql = (const char*)g_Ql + (size_t)(b * Tz + w0) * 256;
        for (int i = tid; i < 128 * 16; i += 256) {
            int r = i >> 4, c = i & 15;
            uint32_t so = (uint32_t)r * RSTRIDE + c * 16;
            size_t go = (size_t)r * 256 + c * 16;
            cp16(sb + OFF_QH + so, qh + go);
            cp16(sb + OFF_QL + so, ql + go);
        }
        const char* kh = (const char*)g_Kh + (size_t)(b * KTOT + kbase) * 256;
        const char* kl = (const char*)g_Kl + (size_t)(b * KTOT + kbase) * 256;
        for (int i = tid; i < 255 * 16; i += 256) {
            int r = i >> 4, c = i & 15;
            uint32_t so = (uint32_t)r * RSTRIDE + c * 16;
            size_t go = (size_t)r * 256 + c * 16;
            cp16(sb + OFF_KH + so, kh + go);
            cp16(sb + OFF_KL + so, kl + go);
        }
    }
    CP_WAIT_ALL();
    // zero row 255 of the K buffers (referenced by ntg=31, masked in scatter)
    if (tid < 17) {
        *(uint4*)(sm + OFF_KH + 255 * RSTRIDE + tid * 16) = make_uint4(0, 0, 0, 0);
        *(uint4*)(sm + OFF_KL + 255 * RSTRIDE + tid * 16) = make_uint4(0, 0, 0, 0);
    }
    __syncthreads();

    // ldmatrix lane-address components
    const uint32_t m8  = lane >> 3;           // matrix id 0..3
    const uint32_t mr  = lane & 7;            // row within matrix
    // A: m0(r0,c0) m1(r8,c0) m2(r0,c8) m3(r8,c8)
    const uint32_t a_row  = 16u * wid + ((m8 & 1) << 3) + mr;
    const uint32_t a_colb = ((m8 >> 1) << 3) * 2;
    const uint32_t aH = sb + OFF_QH + a_row * RSTRIDE + a_colb;
    const uint32_t aL = sb + OFF_QL + a_row * RSTRIDE + a_colb;
    // B: m0(n0,k0) m1(n0,k8) m2(n8,k0) m3(n8,k8) -> 2 n-tiles per ldsm4
    const uint32_t b_off = (((m8 >> 1) << 3) + mr) * RSTRIDE + ((m8 & 1) << 3) * 2;

    // ================= band: 18 n-tiles (ntg = 2*wid .. 2*wid+17) =================
    float acc[18][4];
    #pragma unroll
    for (int t = 0; t < 18; t++)
        #pragma unroll
        for (int e = 0; e < 4; e++) acc[t][e] = 0.0f;

    #pragma unroll 1
    for (int kt = 0; kt < 8; kt++) {
        uint32_t ah[4], al[4];
        ldsm4(ah, aH + kt * 32);
        ldsm4(al, aL + kt * 32);
        #pragma unroll
        for (int p = 0; p < 9; p++) {
            uint32_t bb = sb + OFF_KH + (16u * (wid + p)) * RSTRIDE + b_off + kt * 32;
            uint32_t bh[4], bl[4];
            ldsm4(bh, bb);
            ldsm4(bl, bb + (OFF_KL - OFF_KH));
            mma_bf16(acc[2 * p],     ah, bh[0], bh[1]);
            mma_bf16(acc[2 * p],     al, bh[0], bh[1]);
            mma_bf16(acc[2 * p],     ah, bl[0], bl[1]);
            mma_bf16(acc[2 * p + 1], ah, bh[2], bh[3]);
            mma_bf16(acc[2 * p + 1], al, bh[2], bh[3]);
            mma_bf16(acc[2 * p + 1], ah, bl[2], bl[3]);
        }
    }

    // scatter sheared to global: Z[row][n - row]
    float* __restrict__ Zb = Z + ((size_t)b * Tz + w0) * Tz + t0;
    #pragma unroll
    for (int t = 0; t < 18; t++) {
        const int n0 = (2 * wid + t) * 8 + lc;
        #pragma unroll
        for (int h = 0; h < 2; h++) {
            const int row = 16 * wid + lr + h * 8;
            const int j0 = n0 - row;
            if ((unsigned)j0 < 128u)       Zb[(size_t)row * Tz + j0]     = acc[t][2 * h];
            if ((unsigned)(j0 + 1) < 128u) Zb[(size_t)row * Tz + j0 + 1] = acc[t][2 * h + 1];
        }
    }

    // ================= bias: load tile into K buffer, GEMM, RMW Z =================
    __syncthreads();   // all band reads of K buffer complete
    {
        const char* bh = (const char*)g_Bh + (size_t)t0 * 256;
        const char* bl = (const char*)g_Bl + (size_t)t0 * 256;
        for (int i = tid; i < 128 * 16; i += 256) {
            int r = i >> 4, c = i & 15;
            uint32_t so = (uint32_t)r * RSTRIDE + c * 16;
            size_t go = (size_t)r * 256 + c * 16;
            cp16(sb + OFF_KH + so, bh + go);
            cp16(sb + OFF_KL + so, bl + go);
        }
    }
    CP_WAIT_ALL();
    __syncthreads();

    float bacc[16][4];
    #pragma unroll
    for (int t = 0; t < 16; t++)
        #pragma unroll
        for (int e = 0; e < 4; e++) bacc[t][e] = 0.0f;

    #pragma unroll 1
    for (int kt = 0; kt < 8; kt++) {
        uint32_t ah[4], al[4];
        ldsm4(ah, aH + kt * 32);
        ldsm4(al, aL + kt * 32);
        #pragma unroll
        for (int p = 0; p < 8; p++) {
            uint32_t bb = sb + OFF_KH + (16u * p) * RSTRIDE + b_off + kt * 32;
            uint32_t bh[4], bl[4];
            ldsm4(bh, bb);
            ldsm4(bl, bb + (OFF_KL - OFF_KH));
            mma_bf16(bacc[2 * p],     ah, bh[0], bh[1]);
            mma_bf16(bacc[2 * p],     al, bh[0], bh[1]);
            mma_bf16(bacc[2 * p],     ah, bl[0], bl[1]);
            mma_bf16(bacc[2 * p + 1], ah, bh[2], bh[3]);
            mma_bf16(bacc[2 * p + 1], al, bh[2], bh[3]);
            mma_bf16(bacc[2 * p + 1], ah, bl[2], bl[3]);
        }
    }

    // RMW: Z += bias GEMM (band values already in Z; same warp wrote these rows,
    // visibility across lanes guaranteed by the __syncthreads above)
    #pragma unroll
    for (int t = 0; t < 16; t++) {
        const int col = t * 8 + lc;
        #pragma unroll
        for (int h = 0; h < 2; h++) {
            const int row = 16 * wid + lr + h * 8;
            float2* p = (float2*)(Zb + (size_t)row * Tz + col);
            float2 z = *p;
            z.x += bacc[t][2 * h];
            z.y += bacc[t][2 * h + 1];
            *p = z;
        }
    }
}

// ---------------------------------------------------------------------------
extern "C" void kernel_launch(void* const* d_in, const int* in_sizes, int n_in,
                              void* d_out, int out_size)
{
    const float* Q    = (const float*)d_in[0];   // (16, 1024, 128)
    const float* K    = (const float*)d_in[1];   // (16, 2047, 128)
    const float* bias = (const float*)d_in[2];   // (128, 1024)
    float* Z = (float*)d_out;                    // (16, 1024, 1024)

    static int configured = 0;
    if (!configured) {
        cudaFuncSetAttribute(swmm3d_main,
                             cudaFuncAttributeMaxDynamicSharedMemorySize, SMEM_BYTES);
        configured = 1;
    }

    conv_qk_kernel<<<6142, 256>>>(Q, K);           // 1572352 threads, exact
    conv_bias_kernel<<<512, 256>>>(bias);
    dim3 grid(Tz / 128, Tz / 128, Bz);             // (8, 8, 16) = 1024 CTAs
    swmm3d_main<<<grid, 256, SMEM_BYTES>>>(Z);
}

// round 5
// speedup vs baseline: 1.7751x; 1.4079x over previous
#include <cuda_runtime.h>
#include <cuda_bf16.h>
#include <stdint.h>

// SlidingWindowMatrixMult3D via mma.sync bf16, 3-pass fp32 emulation.
// Z[b,w,t] = sum_c Q[b,w,c]*K[b,w+t,c] + sum_c Q[b,w,c]*bias[c,t]
// B=16, T=1024, C=128.
//
// R5: 64x64 output tiles, 102KB smem -> 2 CTAs/SM so load/RMW phases of one
// CTA overlap MMA phases of the other. Pre-pass converts fp32 -> bf16 hi/lo
// into __device__ globals. Band scattered sheared directly to Z; bias GEMM
// then RMWs Z.

#define Bz 16
#define Tz 1024
#define Cz 128
#define KTOT 2047

// ---- global bf16 scratch ----
__device__ __nv_bfloat16 g_Qh[Bz * Tz * Cz];
__device__ __nv_bfloat16 g_Ql[Bz * Tz * Cz];
__device__ __nv_bfloat16 g_Kh[Bz * KTOT * Cz];
__device__ __nv_bfloat16 g_Kl[Bz * KTOT * Cz];
__device__ __nv_bfloat16 g_Bh[Tz * Cz];     // transposed: [t][c]
__device__ __nv_bfloat16 g_Bl[Tz * Cz];

// ---- smem layout: rows of 128 bf16 padded to 272 B ----
#define RSTRIDE 272u
#define OFF_QH 0u
#define OFF_QL 17408u
#define OFF_KH 34816u            // 128-row buffer (K band 127 rows / bias 64 rows)
#define OFF_KL 69632u
#define SMEM_BYTES 104448u       // 102 KB -> 2 CTAs/SM

// ---------------------------------------------------------------------------
__device__ __forceinline__ uint32_t cvta_sh(const void* p) {
    uint32_t a;
    asm("{ .reg .u64 t; cvta.to.shared.u64 t, %1; cvt.u32.u64 %0, t; }"
        : "=r"(a) : "l"(p));
    return a;
}
__device__ __forceinline__ void cp16(uint32_t d, const void* s) {
    asm volatile("cp.async.ca.shared.global [%0], [%1], 16;" :: "r"(d), "l"(s));
}
#define CP_WAIT_ALL() asm volatile("cp.async.wait_all;" ::: "memory")

__device__ __forceinline__ void ldsm4(uint32_t* r, uint32_t a) {
    asm volatile("ldmatrix.sync.aligned.m8n8.x4.shared.b16 {%0,%1,%2,%3}, [%4];"
                 : "=r"(r[0]), "=r"(r[1]), "=r"(r[2]), "=r"(r[3]) : "r"(a));
}
__device__ __forceinline__ void ldsm2(uint32_t* r, uint32_t a) {
    asm volatile("ldmatrix.sync.aligned.m8n8.x2.shared.b16 {%0,%1}, [%2];"
                 : "=r"(r[0]), "=r"(r[1]) : "r"(a));
}
__device__ __forceinline__ void mma_bf16(float* d, const uint32_t* a,
                                         uint32_t b0, uint32_t b1) {
    asm volatile(
        "mma.sync.aligned.m16n8k16.row.col.f32.bf16.bf16.f32 "
        "{%0,%1,%2,%3}, {%4,%5,%6,%7}, {%8,%9}, {%0,%1,%2,%3};"
        : "+f"(d[0]), "+f"(d[1]), "+f"(d[2]), "+f"(d[3])
        : "r"(a[0]), "r"(a[1]), "r"(a[2]), "r"(a[3]), "r"(b0), "r"(b1));
}
// 3-pass fp32-emulated MMA on one n8 tile
__device__ __forceinline__ void mma3(float* d, const uint32_t* ah, const uint32_t* al,
                                     uint32_t bh0, uint32_t bh1,
                                     uint32_t bl0, uint32_t bl1) {
    mma_bf16(d, ah, bh0, bh1);
    mma_bf16(d, al, bh0, bh1);
    mma_bf16(d, ah, bl0, bl1);
}

// ---------------------------------------------------------------------------
__global__ void conv_qk_kernel(const float* __restrict__ Q,
                               const float* __restrict__ K)
{
    const int nQ = Bz * Tz * Cz / 4;
    const int nK = Bz * KTOT * Cz / 4;
    int i = blockIdx.x * blockDim.x + threadIdx.x;
    if (i >= nQ + nK) return;
    const float4* src;
    uint2 *dh, *dl;
    int j;
    if (i < nQ) { src = (const float4*)Q; dh = (uint2*)g_Qh; dl = (uint2*)g_Ql; j = i; }
    else        { src = (const float4*)K; dh = (uint2*)g_Kh; dl = (uint2*)g_Kl; j = i - nQ; }
    float4 v = __ldg(src + j);
    __nv_bfloat162 h01 = __floats2bfloat162_rn(v.x, v.y);
    __nv_bfloat162 h23 = __floats2bfloat162_rn(v.z, v.w);
    float2 f01 = __bfloat1622float2(h01);
    float2 f23 = __bfloat1622float2(h23);
    __nv_bfloat162 l01 = __floats2bfloat162_rn(v.x - f01.x, v.y - f01.y);
    __nv_bfloat162 l23 = __floats2bfloat162_rn(v.z - f23.x, v.w - f23.y);
    uint2 h, l;
    h.x = *(uint32_t*)&h01; h.y = *(uint32_t*)&h23;
    l.x = *(uint32_t*)&l01; l.y = *(uint32_t*)&l23;
    dh[j] = h;
    dl[j] = l;
}

__global__ void conv_bias_kernel(const float* __restrict__ bias)
{
    int o = blockIdx.x * blockDim.x + threadIdx.x;
    if (o >= Tz * Cz) return;
    int t = o >> 7, c = o & 127;
    float v = __ldg(bias + c * Tz + t);
    __nv_bfloat16 h = __float2bfloat16(v);
    g_Bh[o] = h;
    g_Bl[o] = __float2bfloat16(v - __bfloat162float(h));
}

// ---------------------------------------------------------------------------
__global__ void __launch_bounds__(256, 2)
swmm3d_main(float* __restrict__ Z)
{
    extern __shared__ char sm[];
    const uint32_t sb = cvta_sh(sm);

    const int tid  = threadIdx.x;
    const int wid  = tid >> 5;
    const int lane = tid & 31;
    const int lr = lane >> 2;         // 0..7
    const int lc = (lane & 3) * 2;    // 0,2,4,6
    const int mt = wid >> 1;          // m-tile 0..3 (rows 16*mt..16*mt+15)
    const int s  = wid & 1;           // n-split within m-tile

    const int b  = blockIdx.z;
    const int w0 = blockIdx.y * 64;
    const int t0 = blockIdx.x * 64;
    const int kbase = w0 + t0;

    // ---- load Q (64 rows) + K band (127 rows) ----
    {
        const char* qh = (const char*)g_Qh + (size_t)(b * Tz + w0) * 256;
        const char* ql = (const char*)g_Ql + (size_t)(b * Tz + w0) * 256;
        for (int i = tid; i < 64 * 16; i += 256) {
            int r = i >> 4, c = i & 15;
            uint32_t so = (uint32_t)r * RSTRIDE + c * 16;
            size_t go = (size_t)r * 256 + c * 16;
            cp16(sb + OFF_QH + so, qh + go);
            cp16(sb + OFF_QL + so, ql + go);
        }
        const char* kh = (const char*)g_Kh + (size_t)(b * KTOT + kbase) * 256;
        const char* kl = (const char*)g_Kl + (size_t)(b * KTOT + kbase) * 256;
        for (int i = tid; i < 127 * 16; i += 256) {
            int r = i >> 4, c = i & 15;
            uint32_t so = (uint32_t)r * RSTRIDE + c * 16;
            size_t go = (size_t)r * 256 + c * 16;
            cp16(sb + OFF_KH + so, kh + go);
            cp16(sb + OFF_KL + so, kl + go);
        }
    }
    CP_WAIT_ALL();
    if (tid < 34) {    // zero buffer row 127 (touched by n-tile 15, masked on scatter)
        uint32_t off = (tid < 17 ? OFF_KH : OFF_KL) + 127u * RSTRIDE + (tid % 17) * 16;
        *(uint4*)(sm + off) = make_uint4(0, 0, 0, 0);
    }
    __syncthreads();

    // ldmatrix addresses
    const uint32_t m8 = lane >> 3, mr = lane & 7;
    const uint32_t a_row = 16u * mt + ((m8 & 1) << 3) + mr;
    const uint32_t aH = sb + OFF_QH + a_row * RSTRIDE + (m8 >> 1) * 16;
    const uint32_t aL = aH + (OFF_QL - OFF_QH);
    const uint32_t b4_off = ((m8 >> 1) * 8 + mr) * RSTRIDE + (m8 & 1) * 16;
    const uint32_t l16 = lane & 15;
    const uint32_t b2_off = (l16 & 7) * RSTRIDE + (l16 >> 3) * 16;

    // ================= band: 5 n-tiles, gnt0 = 2*mt + 5*s =================
    const int gnt0 = 2 * mt + 5 * s;
    float acc[5][4];
    #pragma unroll
    for (int u = 0; u < 5; u++)
        #pragma unroll
        for (int e = 0; e < 4; e++) acc[u][e] = 0.0f;

    #pragma unroll 1
    for (int kt = 0; kt < 8; kt++) {
        uint32_t ah[4], al[4];
        ldsm4(ah, aH + kt * 32);
        ldsm4(al, aL + kt * 32);
        // tiles u=0,1 and u=2,3 via ldsm4 pairs
        #pragma unroll
        for (int pp = 0; pp < 2; pp++) {
            uint32_t bb = sb + OFF_KH + (uint32_t)(gnt0 + 2 * pp) * 8 * RSTRIDE
                        + b4_off + kt * 32;
            uint32_t bh[4], bl[4];
            ldsm4(bh, bb);
            ldsm4(bl, bb + (OFF_KL - OFF_KH));
            mma3(acc[2 * pp],     ah, al, bh[0], bh[1], bl[0], bl[1]);
            mma3(acc[2 * pp + 1], ah, al, bh[2], bh[3], bl[2], bl[3]);
        }
        // tile u=4 via ldsm2
        {
            uint32_t bb = sb + OFF_KH + (uint32_t)(gnt0 + 4) * 8 * RSTRIDE
                        + b2_off + kt * 32;
            uint32_t bh[2], bl[2];
            ldsm2(bh, bb);
            ldsm2(bl, bb + (OFF_KL - OFF_KH));
            mma3(acc[4], ah, al, bh[0], bh[1], bl[0], bl[1]);
        }
    }

    // scatter sheared to Z: Z[row][n - row]
    float* __restrict__ Zb = Z + ((size_t)b * Tz + w0) * Tz + t0;
    #pragma unroll
    for (int u = 0; u < 5; u++) {
        const int n0 = (gnt0 + u) * 8 + lc;
        #pragma unroll
        for (int h = 0; h < 2; h++) {
            const int row = 16 * mt + lr + 8 * h;
            const int j0 = n0 - row;
            if ((unsigned)j0 < 64u)       Zb[(size_t)row * Tz + j0]     = acc[u][2 * h];
            if ((unsigned)(j0 + 1) < 64u) Zb[(size_t)row * Tz + j0 + 1] = acc[u][2 * h + 1];
        }
    }

    // ================= bias: 4 n-tiles, local bt0 = 4*s =================
    __syncthreads();   // band reads of K buffer + Z writes complete
    {
        const char* bh = (const char*)g_Bh + (size_t)t0 * 256;
        const char* bl = (const char*)g_Bl + (size_t)t0 * 256;
        for (int i = tid; i < 64 * 16; i += 256) {
            int r = i >> 4, c = i & 15;
            uint32_t so = (uint32_t)r * RSTRIDE + c * 16;
            size_t go = (size_t)r * 256 + c * 16;
            cp16(sb + OFF_KH + so, bh + go);
            cp16(sb + OFF_KL + so, bl + go);
        }
    }
    CP_WAIT_ALL();
    __syncthreads();

    float bacc[4][4];
    #pragma unroll
    for (int u = 0; u < 4; u++)
        #pragma unroll
        for (int e = 0; e < 4; e++) bacc[u][e] = 0.0f;

    #pragma unroll 1
    for (int kt = 0; kt < 8; kt++) {
        uint32_t ah[4], al[4];
        ldsm4(ah, aH + kt * 32);
        ldsm4(al, aL + kt * 32);
        #pragma unroll
        for (int pp = 0; pp < 2; pp++) {
            uint32_t bb = sb + OFF_KH + (uint32_t)(4 * s + 2 * pp) * 8 * RSTRIDE
                        + b4_off + kt * 32;
            uint32_t bh[4], bl[4];
            ldsm4(bh, bb);
            ldsm4(bl, bb + (OFF_KL - OFF_KH));
            mma3(bacc[2 * pp],     ah, al, bh[0], bh[1], bl[0], bl[1]);
            mma3(bacc[2 * pp + 1], ah, al, bh[2], bh[3], bl[2], bl[3]);
        }
    }

    // RMW: Z += bias GEMM (band values visible via the __syncthreads above)
    #pragma unroll
    for (int u = 0; u < 4; u++) {
        const int col = (4 * s + u) * 8 + lc;
        #pragma unroll
        for (int h = 0; h < 2; h++) {
            const int row = 16 * mt + lr + 8 * h;
            float2* p = (float2*)(Zb + (size_t)row * Tz + col);
            float2 z = *p;
            z.x += bacc[u][2 * h];
            z.y += bacc[u][2 * h + 1];
            *p = z;
        }
    }
}

// ---------------------------------------------------------------------------
extern "C" void kernel_launch(void* const* d_in, const int* in_sizes, int n_in,
                              void* d_out, int out_size)
{
    const float* Q    = (const float*)d_in[0];   // (16, 1024, 128)
    const float* K    = (const float*)d_in[1];   // (16, 2047, 128)
    const float* bias = (const float*)d_in[2];   // (128, 1024)
    float* Z = (float*)d_out;                    // (16, 1024, 1024)

    static int configured = 0;
    if (!configured) {
        cudaFuncSetAttribute(swmm3d_main,
                             cudaFuncAttributeMaxDynamicSharedMemorySize, SMEM_BYTES);
        configured = 1;
    }

    conv_qk_kernel<<<6142, 256>>>(Q, K);
    conv_bias_kernel<<<512, 256>>>(bias);
    dim3 grid(Tz / 64, Tz / 64, Bz);    // (16, 16, 16) = 4096 CTAs
    swmm3d_main<<<grid, 256, SMEM_BYTES>>>(Z);
}

// round 6
// speedup vs baseline: 1.8553x; 1.0451x over previous
#include <cuda_runtime.h>
#include <cuda_bf16.h>
#include <stdint.h>

// SlidingWindowMatrixMult3D via mma.sync bf16, 3-pass fp32 emulation.
// Z[b,w,t] = sum_c Q[b,w,c]*K[b,w+t,c] + sum_c Q[b,w,c]*bias[c,t]
// B=16, T=1024, C=128.
//
// R6: strip-mined CTAs. Each CTA: 64 w-rows x 256 t-cols (4 sub-tiles of
// 64x64). Q loaded once; K slides through a 128-row ring buffer (64 new rows
// per sub-tile); bias tiles staged in the ring's dead slots. Band scattered
// sheared to Z, bias GEMM RMWs Z. 102KB smem -> 2 CTAs/SM.

#define Bz 16
#define Tz 1024
#define Cz 128
#define KTOT 2047

// ---- global bf16 scratch ----
__device__ __nv_bfloat16 g_Qh[Bz * Tz * Cz];
__device__ __nv_bfloat16 g_Ql[Bz * Tz * Cz];
__device__ __nv_bfloat16 g_Kh[Bz * KTOT * Cz];
__device__ __nv_bfloat16 g_Kl[Bz * KTOT * Cz];
__device__ __nv_bfloat16 g_Bh[Tz * Cz];     // transposed: [t][c]
__device__ __nv_bfloat16 g_Bl[Tz * Cz];

// ---- smem: rows of 128 bf16 padded to 272 B ----
#define RSTRIDE 272u
#define OFF_QH 0u
#define OFF_QL 17408u
#define OFF_KH 34816u            // 128-slot ring (hi)
#define OFF_KL 69632u            // 128-slot ring (lo)
#define DHL    34816u            // hi->lo delta
#define SMEM_BYTES 104448u       // 102 KB -> 2 CTAs/SM

// ---------------------------------------------------------------------------
__device__ __forceinline__ uint32_t cvta_sh(const void* p) {
    uint32_t a;
    asm("{ .reg .u64 t; cvta.to.shared.u64 t, %1; cvt.u32.u64 %0, t; }"
        : "=r"(a) : "l"(p));
    return a;
}
__device__ __forceinline__ void cp16(uint32_t d, const void* s) {
    asm volatile("cp.async.ca.shared.global [%0], [%1], 16;" :: "r"(d), "l"(s));
}
#define CP_WAIT_ALL() asm volatile("cp.async.wait_all;" ::: "memory")

__device__ __forceinline__ void ldsm4(uint32_t* r, uint32_t a) {
    asm volatile("ldmatrix.sync.aligned.m8n8.x4.shared.b16 {%0,%1,%2,%3}, [%4];"
                 : "=r"(r[0]), "=r"(r[1]), "=r"(r[2]), "=r"(r[3]) : "r"(a));
}
__device__ __forceinline__ void ldsm2(uint32_t* r, uint32_t a) {
    asm volatile("ldmatrix.sync.aligned.m8n8.x2.shared.b16 {%0,%1}, [%2];"
                 : "=r"(r[0]), "=r"(r[1]) : "r"(a));
}
__device__ __forceinline__ void mma_bf16(float* d, const uint32_t* a,
                                         uint32_t b0, uint32_t b1) {
    asm volatile(
        "mma.sync.aligned.m16n8k16.row.col.f32.bf16.bf16.f32 "
        "{%0,%1,%2,%3}, {%4,%5,%6,%7}, {%8,%9}, {%0,%1,%2,%3};"
        : "+f"(d[0]), "+f"(d[1]), "+f"(d[2]), "+f"(d[3])
        : "r"(a[0]), "r"(a[1]), "r"(a[2]), "r"(a[3]), "r"(b0), "r"(b1));
}
__device__ __forceinline__ void mma3(float* d, const uint32_t* ah, const uint32_t* al,
                                     uint32_t bh0, uint32_t bh1,
                                     uint32_t bl0, uint32_t bl1) {
    mma_bf16(d, ah, bh0, bh1);
    mma_bf16(d, al, bh0, bh1);
    mma_bf16(d, ah, bl0, bl1);
}

// ---------------------------------------------------------------------------
// merged pre-pass: Q, K (float4 path) + bias transpose (scalar path)
__global__ void conv_all_kernel(const float* __restrict__ Q,
                                const float* __restrict__ K,
                                const float* __restrict__ bias)
{
    const int nQ = Bz * Tz * Cz / 4;        // 524288
    const int nK = Bz * KTOT * Cz / 4;      // 1048064
    const int nB = Tz * Cz / 4;             // 32768 (4 elems each)
    int i = blockIdx.x * blockDim.x + threadIdx.x;
    if (i < nQ + nK) {
        const float4* src;
        uint2 *dh, *dl;
        int j;
        if (i < nQ) { src = (const float4*)Q; dh = (uint2*)g_Qh; dl = (uint2*)g_Ql; j = i; }
        else        { src = (const float4*)K; dh = (uint2*)g_Kh; dl = (uint2*)g_Kl; j = i - nQ; }
        float4 v = __ldg(src + j);
        __nv_bfloat162 h01 = __floats2bfloat162_rn(v.x, v.y);
        __nv_bfloat162 h23 = __floats2bfloat162_rn(v.z, v.w);
        float2 f01 = __bfloat1622float2(h01);
        float2 f23 = __bfloat1622float2(h23);
        __nv_bfloat162 l01 = __floats2bfloat162_rn(v.x - f01.x, v.y - f01.y);
        __nv_bfloat162 l23 = __floats2bfloat162_rn(v.z - f23.x, v.w - f23.y);
        uint2 h, l;
        h.x = *(uint32_t*)&h01; h.y = *(uint32_t*)&h23;
        l.x = *(uint32_t*)&l01; l.y = *(uint32_t*)&l23;
        dh[j] = h;
        dl[j] = l;
    } else if (i < nQ + nK + nB) {
        int u = i - nQ - nK;                // 4 consecutive t-major outputs
        int o = u * 4;
        int t = o >> 7, c = o & 127;        // c..c+3 within row t
        float4 v;
        v.x = __ldg(bias + (c + 0) * Tz + t);
        v.y = __ldg(bias + (c + 1) * Tz + t);
        v.z = __ldg(bias + (c + 2) * Tz + t);
        v.w = __ldg(bias + (c + 3) * Tz + t);
        __nv_bfloat162 h01 = __floats2bfloat162_rn(v.x, v.y);
        __nv_bfloat162 h23 = __floats2bfloat162_rn(v.z, v.w);
        float2 f01 = __bfloat1622float2(h01);
        float2 f23 = __bfloat1622float2(h23);
        __nv_bfloat162 l01 = __floats2bfloat162_rn(v.x - f01.x, v.y - f01.y);
        __nv_bfloat162 l23 = __floats2bfloat162_rn(v.z - f23.x, v.w - f23.y);
        uint2 h, l;
        h.x = *(uint32_t*)&h01; h.y = *(uint32_t*)&h23;
        l.x = *(uint32_t*)&l01; l.y = *(uint32_t*)&l23;
        ((uint2*)g_Bh)[u] = h;
        ((uint2*)g_Bl)[u] = l;
    }
}

// ---------------------------------------------------------------------------
__global__ void __launch_bounds__(256, 2)
swmm3d_main(float* __restrict__ Z)
{
    extern __shared__ char sm[];
    const uint32_t sb = cvta_sh(sm);

    const int tid  = threadIdx.x;
    const int wid  = tid >> 5;
    const int lane = tid & 31;
    const int lr = lane >> 2;
    const int lc = (lane & 3) * 2;
    const int mt = wid >> 1;          // rows 16*mt .. 16*mt+15
    const int s  = wid & 1;

    const int b  = blockIdx.x >> 4;
    const int ws = blockIdx.x & 15;   // w-strip
    const int w0 = ws * 64;
    const int t0 = blockIdx.y * 256;  // t-strip base
    const int kbase = w0 + t0;

    // ---- initial loads: Q (64 rows), K ring rel rows [0,126] ----
    {
        const char* qh = (const char*)g_Qh + (size_t)(b * Tz + w0) * 256;
        for (int i = tid; i < 64 * 16; i += 256) {
            int r = i >> 4, c = i & 15;
            uint32_t so = (uint32_t)r * RSTRIDE + c * 16;
            size_t go = (size_t)r * 256 + c * 16;
            cp16(sb + OFF_QH + so, qh + go);
            cp16(sb + OFF_QL + so, qh + (size_t)(g_Ql - g_Qh) * 2 + go);
        }
        const char* kh = (const char*)g_Kh + (size_t)(b * KTOT + kbase) * 256;
        const char* kl = (const char*)g_Kl + (size_t)(b * KTOT + kbase) * 256;
        for (int i = tid; i < 127 * 16; i += 256) {
            int r = i >> 4, c = i & 15;
            uint32_t so = (uint32_t)r * RSTRIDE + c * 16;
            size_t go = (size_t)r * 256 + c * 16;
            cp16(sb + OFF_KH + so, kh + go);
            cp16(sb + OFF_KL + so, kl + go);
        }
    }

    // ldmatrix lane components
    const uint32_t m8 = lane >> 3, mr = lane & 7;
    const uint32_t a_row = 16u * mt + ((m8 & 1) << 3) + mr;
    const uint32_t aH = sb + OFF_QH + a_row * RSTRIDE + (m8 >> 1) * 16;
    const uint32_t aL = aH + (OFF_QL - OFF_QH);
    const int rB  = (int)((m8 >> 1) * 8 + mr);   // B n-row within ldsm4 group
    const uint32_t cB = (m8 & 1) * 16;
    const uint32_t l16 = lane & 15;
    const int rB2 = (int)(l16 & 7);
    const uint32_t cB2 = (l16 >> 3) * 16;

    const int gnt0 = 2 * mt + 5 * s;            // band n-tile base (per warp)

    const float* Zbase = Z;  // silence unused warnings pattern
    (void)Zbase;

    #pragma unroll 1
    for (int j = 0; j < 4; j++) {
        const int wb = 64 * j;                  // window base (rel K row)
        float* __restrict__ Zb = Z + ((size_t)b * Tz + w0) * Tz + t0 + wb;

        CP_WAIT_ALL();
        __syncthreads();                         // K window ready

        // ---- band MMA: 5 n-tiles ----
        float acc[5][4];
        #pragma unroll
        for (int u = 0; u < 5; u++)
            #pragma unroll
            for (int e = 0; e < 4; e++) acc[u][e] = 0.0f;

        // per-lane ring addresses for this sub-tile
        uint32_t bb0 = sb + OFF_KH + (uint32_t)((wb + gnt0 * 8 + rB) & 127) * RSTRIDE + cB;
        uint32_t bb1 = sb + OFF_KH + (uint32_t)((wb + (gnt0 + 2) * 8 + rB) & 127) * RSTRIDE + cB;
        uint32_t bb2 = sb + OFF_KH + (uint32_t)((wb + (gnt0 + 4) * 8 + rB2) & 127) * RSTRIDE + cB2;

        #pragma unroll 1
        for (int kt = 0; kt < 8; kt++) {
            uint32_t ah[4], al[4];
            ldsm4(ah, aH + kt * 32);
            ldsm4(al, aL + kt * 32);
            uint32_t bh[4], bl[4];
            ldsm4(bh, bb0 + kt * 32);
            ldsm4(bl, bb0 + DHL + kt * 32);
            mma3(acc[0], ah, al, bh[0], bh[1], bl[0], bl[1]);
            mma3(acc[1], ah, al, bh[2], bh[3], bl[2], bl[3]);
            ldsm4(bh, bb1 + kt * 32);
            ldsm4(bl, bb1 + DHL + kt * 32);
            mma3(acc[2], ah, al, bh[0], bh[1], bl[0], bl[1]);
            mma3(acc[3], ah, al, bh[2], bh[3], bl[2], bl[3]);
            uint32_t b2h[2], b2l[2];
            ldsm2(b2h, bb2 + kt * 32);
            ldsm2(b2l, bb2 + DHL + kt * 32);
            mma3(acc[4], ah, al, b2h[0], b2h[1], b2l[0], b2l[1]);
        }
        __syncthreads();                         // dead ring slots now free

        // ---- stage bias tile j into dead slots (rel rows [wb, wb+63]) ----
        {
            const char* bh = (const char*)g_Bh + (size_t)(t0 + wb) * 256;
            const char* bl = (const char*)g_Bl + (size_t)(t0 + wb) * 256;
            for (int i = tid; i < 64 * 16; i += 256) {
                int r = i >> 4, c = i & 15;
                uint32_t so = (uint32_t)((wb + r) & 127) * RSTRIDE + c * 16;
                size_t go = (size_t)r * 256 + c * 16;
                cp16(sb + OFF_KH + so, bh + go);
                cp16(sb + OFF_KL + so, bl + go);
            }
        }

        // ---- scatter band sheared to Z (overlaps bias loads) ----
        #pragma unroll
        for (int u = 0; u < 5; u++) {
            const int n0 = (gnt0 + u) * 8 + lc;
            #pragma unroll
            for (int h = 0; h < 2; h++) {
                const int row = 16 * mt + lr + 8 * h;
                const int j0 = n0 - row;
                if ((unsigned)j0 < 64u)       Zb[(size_t)row * Tz + j0]     = acc[u][2 * h];
                if ((unsigned)(j0 + 1) < 64u) Zb[(size_t)row * Tz + j0 + 1] = acc[u][2 * h + 1];
            }
        }

        CP_WAIT_ALL();
        __syncthreads();                         // bias ready

        // ---- bias MMA: 4 n-tiles ----
        float bacc[4][4];
        #pragma unroll
        for (int u = 0; u < 4; u++)
            #pragma unroll
            for (int e = 0; e < 4; e++) bacc[u][e] = 0.0f;

        uint32_t pb0 = sb + OFF_KH + (uint32_t)((wb + (4 * s) * 8 + rB) & 127) * RSTRIDE + cB;
        uint32_t pb1 = sb + OFF_KH + (uint32_t)((wb + (4 * s + 2) * 8 + rB) & 127) * RSTRIDE + cB;

        #pragma unroll 1
        for (int kt = 0; kt < 8; kt++) {
            uint32_t ah[4], al[4];
            ldsm4(ah, aH + kt * 32);
            ldsm4(al, aL + kt * 32);
            uint32_t bh[4], bl[4];
            ldsm4(bh, pb0 + kt * 32);
            ldsm4(bl, pb0 + DHL + kt * 32);
            mma3(bacc[0], ah, al, bh[0], bh[1], bl[0], bl[1]);
            mma3(bacc[1], ah, al, bh[2], bh[3], bl[2], bl[3]);
            ldsm4(bh, pb1 + kt * 32);
            ldsm4(bl, pb1 + DHL + kt * 32);
            mma3(bacc[2], ah, al, bh[0], bh[1], bl[0], bl[1]);
            mma3(bacc[3], ah, al, bh[2], bh[3], bl[2], bl[3]);
        }
        __syncthreads();                         // bias slot reads done

        // ---- prefetch next 64 K rows (rel [wb+127, wb+190]) ----
        if (j < 3) {
            const char* kh = (const char*)g_Kh + (size_t)(b * KTOT + kbase) * 256;
            const char* kl = (const char*)g_Kl + (size_t)(b * KTOT + kbase) * 256;
            for (int i = tid; i < 64 * 16; i += 256) {
                int r = i >> 4, c = i & 15;
                int rel = wb + 127 + r;
                uint32_t so = (uint32_t)(rel & 127) * RSTRIDE + c * 16;
                size_t go = (size_t)rel * 256 + c * 16;
                cp16(sb + OFF_KH + so, kh + go);
                cp16(sb + OFF_KL + so, kl + go);
            }
        }

        // ---- RMW: Z += bias GEMM (overlaps K prefetch) ----
        #pragma unroll
        for (int u = 0; u < 4; u++) {
            const int col = (4 * s + u) * 8 + lc;
            #pragma unroll
            for (int h = 0; h < 2; h++) {
                const int row = 16 * mt + lr + 8 * h;
                float2* p = (float2*)(Zb + (size_t)row * Tz + col);
                float2 z = *p;
                z.x += bacc[u][2 * h];
                z.y += bacc[u][2 * h + 1];
                *p = z;
            }
        }
    }
}

// ---------------------------------------------------------------------------
extern "C" void kernel_launch(void* const* d_in, const int* in_sizes, int n_in,
                              void* d_out, int out_size)
{
    const float* Q    = (const float*)d_in[0];   // (16, 1024, 128)
    const float* K    = (const float*)d_in[1];   // (16, 2047, 128)
    const float* bias = (const float*)d_in[2];   // (128, 1024)
    float* Z = (float*)d_out;                    // (16, 1024, 1024)

    static int configured = 0;
    if (!configured) {
        cudaFuncSetAttribute(swmm3d_main,
                             cudaFuncAttributeMaxDynamicSharedMemorySize, SMEM_BYTES);
        configured = 1;
    }

    // pre-pass: 524288 + 1048064 + 32768 = 1605120 threads
    conv_all_kernel<<<6270, 256>>>(Q, K, bias);

    dim3 grid(256, 4, 1);   // x = b*16 + w-strip (adjacent x share K in L2), y = t-strip
    swmm3d_main<<<grid, 256, SMEM_BYTES>>>(Z);
}